// round 1
// baseline (speedup 1.0000x reference)
#include <cuda_runtime.h>
#include <math.h>

#define BATCH 1024
#define INF   256
#define OUTF  256
#define NBF   9            // 8 B-spline bases + silu slot
#define KD    (INF * NBF)  // 2304

// Scratch (allocation-free rule: __device__ globals)
__device__ float g_F[BATCH * KD];  // features, row-major [B][KD], k contiguous
__device__ float g_W[OUTF * KD];   // weights,  row-major [O][KD], k contiguous

// ---------------------------------------------------------------------------
// Feature prep: cubic B-spline basis (Cox–de Boor, exactly mirroring the
// reference recursion) + silu(x). One thread per (b, i).
// ---------------------------------------------------------------------------
__global__ void prep_f_kernel(const float* __restrict__ x,
                              const float* __restrict__ grid) {
    int t = blockIdx.x * blockDim.x + threadIdx.x;
    if (t >= BATCH * INF) return;
    float xv = x[t];

    float g[12];
#pragma unroll
    for (int j = 0; j < 12; j++) g[j] = __ldg(grid + j);

    float bas[11];
#pragma unroll
    for (int j = 0; j < 11; j++)
        bas[j] = (xv >= g[j] && xv < g[j + 1]) ? 1.0f : 0.0f;

#pragma unroll
    for (int p = 1; p <= 3; p++) {
        int n = 11 - p;
#pragma unroll
        for (int j = 0; j < 10; j++) {
            if (j < n) {
                float ld = fmaxf(g[j + p] - g[j], 1e-8f);
                float rd = fmaxf(g[j + p + 1] - g[j + 1], 1e-8f);
                // forward in-place is safe: bas[j] uses old bas[j], bas[j+1]
                bas[j] = (xv - g[j]) / ld * bas[j]
                       + (g[j + p + 1] - xv) / rd * bas[j + 1];
            }
        }
    }
    // bases[:, -1] += (x >= grid[-k-1])
    bas[7] += (xv >= g[8]) ? 1.0f : 0.0f;

    float si = xv / (1.0f + expf(-xv));

    // t*NBF == b*KD + i*NBF  (since t = b*INF + i and KD = INF*NBF)
    float* dst = g_F + (long)t * NBF;
#pragma unroll
    for (int n = 0; n < 8; n++) dst[n] = bas[n];
    dst[8] = si;
}

// ---------------------------------------------------------------------------
// Weight prep: W[o, i*9+n] = coeff[o,i,n] * spline_weight[o,i]  (n<8)
//              W[o, i*9+8] = base_weight[o,i]
// One thread per (o, i); all reads & writes coalesced.
// ---------------------------------------------------------------------------
__global__ void prep_w_kernel(const float* __restrict__ coeff,
                              const float* __restrict__ base_weight,
                              const float* __restrict__ spline_weight) {
    int t = blockIdx.x * blockDim.x + threadIdx.x;
    if (t >= OUTF * INF) return;
    float s = spline_weight[t];
    const float* c = coeff + (long)t * 8;
    float* dst = g_W + (long)t * NBF;
#pragma unroll
    for (int n = 0; n < 8; n++) dst[n] = c[n] * s;
    dst[8] = base_weight[t];
}

// ---------------------------------------------------------------------------
// GEMM: C[1024,256] = F[1024,2304] * W[256,2304]^T
// BM=64, BN=32, BK=32; 256 threads; 4x2 microtile per thread.
// grid = 16 x 8 = 128 blocks -> one full wave on 148 SMs.
// Register-prefetched global->smem pipeline (single smem buffer, 2 syncs).
// ---------------------------------------------------------------------------
#define BM 64
#define BN 32
#define BK 32
#define PADA 68   // BM + 4 pad, keeps 16B alignment, kills store conflicts
#define PADB 36   // BN + 4 pad

__global__ __launch_bounds__(256, 1)
void gemm_kernel(float* __restrict__ C) {
    __shared__ float As[BK][PADA];   // As[k][m]
    __shared__ float Bs[BK][PADB];   // Bs[k][n]

    const int tid = threadIdx.x;
    const int bm = blockIdx.x * BM;
    const int bn = blockIdx.y * BN;

    // compute-phase mapping: 16 threads along m (4 rows each) x 16 along n (2 cols each)
    const int tm = (tid & 15) * 4;
    const int tn = (tid >> 4) * 2;

    // load-phase mapping (float4 slots along K)
    const int ar0 = tid >> 3;                 // rows 0..31
    const int ar1 = (tid >> 3) + 32;          // rows 32..63
    const int ac  = (tid & 7) * 4;            // k offset within tile (float4)
    const int br  = tid >> 3;                 // W rows 0..31
    const int bc  = (tid & 7) * 4;

    const float* Fb = g_F + (long)bm * KD;
    const float* Wb = g_W + (long)bn * KD;

    float acc[4][2] = {};
    float4 ra0, ra1, rb;

    // prologue: tile 0 into registers
    ra0 = *(const float4*)(Fb + (long)ar0 * KD + ac);
    ra1 = *(const float4*)(Fb + (long)ar1 * KD + ac);
    rb  = *(const float4*)(Wb + (long)br  * KD + bc);

    const int NT = KD / BK;   // 72 tiles
    for (int t = 0; t < NT; t++) {
        // commit prefetched registers to smem (transposed: [k][m] / [k][n])
        {
            const float* pa0 = (const float*)&ra0;
            const float* pa1 = (const float*)&ra1;
            const float* pb  = (const float*)&rb;
#pragma unroll
            for (int j = 0; j < 4; j++) {
                As[ac + j][ar0] = pa0[j];
                As[ac + j][ar1] = pa1[j];
                Bs[bc + j][br]  = pb[j];
            }
        }
        __syncthreads();

        // prefetch next tile while computing this one
        if (t + 1 < NT) {
            int k0 = (t + 1) * BK;
            ra0 = *(const float4*)(Fb + (long)ar0 * KD + k0 + ac);
            ra1 = *(const float4*)(Fb + (long)ar1 * KD + k0 + ac);
            rb  = *(const float4*)(Wb + (long)br  * KD + k0 + bc);
        }

#pragma unroll
        for (int k = 0; k < BK; k++) {
            float4 a = *(const float4*)&As[k][tm];
            float2 b = *(const float2*)&Bs[k][tn];
            acc[0][0] += a.x * b.x;  acc[0][1] += a.x * b.y;
            acc[1][0] += a.y * b.x;  acc[1][1] += a.y * b.y;
            acc[2][0] += a.z * b.x;  acc[2][1] += a.z * b.y;
            acc[3][0] += a.w * b.x;  acc[3][1] += a.w * b.y;
        }
        __syncthreads();
    }

#pragma unroll
    for (int mm = 0; mm < 4; mm++)
#pragma unroll
        for (int nn = 0; nn < 2; nn++)
            C[(long)(bm + tm + mm) * OUTF + bn + tn + nn] = acc[mm][nn];
}

// ---------------------------------------------------------------------------
extern "C" void kernel_launch(void* const* d_in, const int* in_sizes, int n_in,
                              void* d_out, int out_size) {
    const float* x             = (const float*)d_in[0];
    const float* grid          = (const float*)d_in[1];
    const float* coeff         = (const float*)d_in[2];
    const float* base_weight   = (const float*)d_in[3];
    const float* spline_weight = (const float*)d_in[4];
    float* out = (float*)d_out;

    prep_f_kernel<<<(BATCH * INF + 255) / 256, 256>>>(x, grid);
    prep_w_kernel<<<(OUTF * INF + 255) / 256, 256>>>(coeff, base_weight, spline_weight);

    dim3 g(BATCH / BM, OUTF / BN);
    gemm_kernel<<<g, 256>>>(out);
}

// round 2
// speedup vs baseline: 1.7166x; 1.7166x over previous
#include <cuda_runtime.h>
#include <cuda_bf16.h>
#include <math.h>
#include <stdint.h>

#define BATCH 1024
#define INF   256
#define OUTF  256
#define NBF   9
#define KD    2304          // INF * NBF, per pass
#define NSPLIT 4
#define BK    32            // k elems per mainloop iter
#define IT_PASS  72         // 2304/32
#define IT_TOTAL 216        // 3 passes
#define IT_SPLIT 54         // 216/4
#define BM 128
#define BN 64
#define NSTAGE 3

// ---- scratch (__device__ globals: allocation-free rule) ----
__device__ __nv_bfloat16 g_Fh[(size_t)BATCH * KD];
__device__ __nv_bfloat16 g_Fl[(size_t)BATCH * KD];
__device__ __nv_bfloat16 g_Wh[(size_t)OUTF * KD];
__device__ __nv_bfloat16 g_Wl[(size_t)OUTF * KD];
__device__ float g_part[NSPLIT][(size_t)BATCH * OUTF];

// ---------------------------------------------------------------------------
// prep_f: cubic B-spline basis + silu, emitted as bf16 hi/lo split.
// Uniform grid: h = 2/GRID_SIZE = 0.4 exactly -> denominators are p*h,
// so use compile-time reciprocals (no per-thread division).
// ---------------------------------------------------------------------------
__global__ void prep_f_kernel(const float* __restrict__ x,
                              const float* __restrict__ grid) {
    int t = blockIdx.x * blockDim.x + threadIdx.x;
    if (t >= BATCH * INF) return;
    float xv = x[t];

    float g[12];
#pragma unroll
    for (int j = 0; j < 12; j++) g[j] = __ldg(grid + j);

    float bas[11];
#pragma unroll
    for (int j = 0; j < 11; j++)
        bas[j] = (xv >= g[j] && xv < g[j + 1]) ? 1.0f : 0.0f;

    const float r1 = 2.5f;            // 1/(1*h), h = 0.4
    const float r2 = 1.25f;           // 1/(2*h)
    const float r3 = 0.83333333333f;  // 1/(3*h)

#pragma unroll
    for (int j = 0; j < 10; j++)      // p = 1
        bas[j] = (xv - g[j]) * r1 * bas[j] + (g[j + 2] - xv) * r1 * bas[j + 1];
#pragma unroll
    for (int j = 0; j < 9; j++)       // p = 2
        bas[j] = (xv - g[j]) * r2 * bas[j] + (g[j + 3] - xv) * r2 * bas[j + 1];
#pragma unroll
    for (int j = 0; j < 8; j++)       // p = 3
        bas[j] = (xv - g[j]) * r3 * bas[j] + (g[j + 4] - xv) * r3 * bas[j + 1];

    bas[7] += (xv >= g[8]) ? 1.0f : 0.0f;

    float e  = __expf(-xv);
    float si = __fdividef(xv, 1.0f + e);

    size_t base = (size_t)t * NBF;    // == b*KD + i*NBF
#pragma unroll
    for (int n = 0; n < 8; n++) {
        float f = bas[n];
        __nv_bfloat16 h = __float2bfloat16(f);
        g_Fh[base + n] = h;
        g_Fl[base + n] = __float2bfloat16(f - __bfloat162float(h));
    }
    {
        __nv_bfloat16 h = __float2bfloat16(si);
        g_Fh[base + 8] = h;
        g_Fl[base + 8] = __float2bfloat16(si - __bfloat162float(h));
    }
}

// ---------------------------------------------------------------------------
// prep_w: W[o, i*9+n] = coeff[o,i,n]*spline_weight[o,i] (n<8), [..+8]=base_w
// emitted as bf16 hi/lo.
// ---------------------------------------------------------------------------
__global__ void prep_w_kernel(const float* __restrict__ coeff,
                              const float* __restrict__ base_weight,
                              const float* __restrict__ spline_weight) {
    int t = blockIdx.x * blockDim.x + threadIdx.x;
    if (t >= OUTF * INF) return;
    float s = spline_weight[t];
    const float* c = coeff + (size_t)t * 8;
    size_t base = (size_t)t * NBF;
#pragma unroll
    for (int n = 0; n < 8; n++) {
        float f = c[n] * s;
        __nv_bfloat16 h = __float2bfloat16(f);
        g_Wh[base + n] = h;
        g_Wl[base + n] = __float2bfloat16(f - __bfloat162float(h));
    }
    {
        float f = base_weight[t];
        __nv_bfloat16 h = __float2bfloat16(f);
        g_Wh[base + 8] = h;
        g_Wl[base + 8] = __float2bfloat16(f - __bfloat162float(h));
    }
}

// ---------------------------------------------------------------------------
// GEMM: C = Fh*Wh^T + Fl*Wh^T + Fh*Wl^T  (3 K-passes, K_eff = 6912)
// mma.sync m16n8k16 bf16, BM=128 BN=64 BK=32, 8 warps, split-K x4,
// cp.async 3-stage pipeline, XOR-swizzled smem.
// grid = (8, 4, 4) = 128 CTAs.
// ---------------------------------------------------------------------------
#define A_TILE_B (BM * 64)      // 128 rows * 64 bytes = 8192
#define B_TILE_B (BN * 64)      // 4096
#define STAGE_B  (A_TILE_B + B_TILE_B)

#define CP16(dst_u32, src_ptr) \
    asm volatile("cp.async.cg.shared.global [%0], [%1], 16;\n" \
                 :: "r"(dst_u32), "l"(src_ptr))

#define LDMX4(r0,r1,r2,r3, addr) \
    asm volatile("ldmatrix.sync.aligned.m8n8.x4.shared.b16 {%0,%1,%2,%3}, [%4];\n" \
                 : "=r"(r0),"=r"(r1),"=r"(r2),"=r"(r3) : "r"(addr))

#define MMA_BF16(d, a, b0_, b1_) \
    asm volatile("mma.sync.aligned.m16n8k16.row.col.f32.bf16.bf16.f32 " \
                 "{%0,%1,%2,%3},{%4,%5,%6,%7},{%8,%9},{%0,%1,%2,%3};\n" \
                 : "+f"(d[0]),"+f"(d[1]),"+f"(d[2]),"+f"(d[3]) \
                 : "r"(a[0]),"r"(a[1]),"r"(a[2]),"r"(a[3]),"r"(b0_),"r"(b1_))

__global__ __launch_bounds__(256, 1)
void gemm_kernel() {
    __shared__ __align__(16) uint8_t smem[NSTAGE * STAGE_B];

    const int tid  = threadIdx.x;
    const int warp = tid >> 5;
    const int lane = tid & 31;
    const int bm = blockIdx.x * BM;
    const int bn = blockIdx.y * BN;
    const int z  = blockIdx.z;
    const int wm = (warp >> 1) * 32;   // 0,32,64,96
    const int wn = (warp & 1) * 32;    // 0,32

    const uint32_t smem_u32 = (uint32_t)__cvta_generic_to_shared(smem);

    // ---- tile loader (one BK=32 slab of A[128] and B[64]) ----
    auto load_tile = [&](int stage, int it) {
        int p  = it / IT_PASS;                      // 0..2
        int k0 = (it - p * IT_PASS) * BK;
        const __nv_bfloat16* Ab = (p == 1) ? g_Fl : g_Fh;
        const __nv_bfloat16* Bb = (p == 2) ? g_Wl : g_Wh;
        uint32_t sA = smem_u32 + stage * STAGE_B;
        uint32_t sB = sA + A_TILE_B;
#pragma unroll
        for (int h = 0; h < 2; h++) {
            int slot = tid + h * 256;               // 512 16B chunks
            int row = slot >> 2, c = slot & 3;
            const __nv_bfloat16* gp = Ab + (size_t)(bm + row) * KD + k0 + c * 8;
            uint32_t d = sA + (uint32_t)((row * 4 + (c ^ ((row >> 1) & 3))) << 4);
            CP16(d, gp);
        }
        {
            int row = tid >> 2, c = tid & 3;        // 256 chunks
            const __nv_bfloat16* gp = Bb + (size_t)(bn + row) * KD + k0 + c * 8;
            uint32_t d = sB + (uint32_t)((row * 4 + (c ^ ((row >> 1) & 3))) << 4);
            CP16(d, gp);
        }
        asm volatile("cp.async.commit_group;\n" ::);
    };

    float acc[2][4][4];
#pragma unroll
    for (int a = 0; a < 2; a++)
#pragma unroll
        for (int b = 0; b < 4; b++)
#pragma unroll
            for (int c = 0; c < 4; c++) acc[a][b][c] = 0.0f;

    const int it0 = z * IT_SPLIT;
    load_tile(0, it0);
    load_tile(1, it0 + 1);

    for (int t = 0; t < IT_SPLIT; t++) {
        int nx = t + NSTAGE - 1;
        if (nx < IT_SPLIT) load_tile((t + 2) % NSTAGE, it0 + nx);
        else asm volatile("cp.async.commit_group;\n" ::);
        asm volatile("cp.async.wait_group 2;\n" ::);
        __syncthreads();

        int stage = t % NSTAGE;
        uint32_t aBase = smem_u32 + stage * STAGE_B;
        uint32_t bBase = aBase + A_TILE_B;

#pragma unroll
        for (int kk = 0; kk < 2; kk++) {
            uint32_t afr[2][4];
#pragma unroll
            for (int mt = 0; mt < 2; mt++) {
                int row = wm + mt * 16 + (lane & 15);
                int ch  = kk * 2 + (lane >> 4);
                uint32_t ad = aBase + (uint32_t)((row * 4 + (ch ^ ((row >> 1) & 3))) << 4);
                LDMX4(afr[mt][0], afr[mt][1], afr[mt][2], afr[mt][3], ad);
            }
            uint32_t bfr[2][4];
#pragma unroll
            for (int nh = 0; nh < 2; nh++) {
                int row = wn + nh * 16 + ((lane >> 4) << 3) + (lane & 7);
                int ch  = kk * 2 + ((lane >> 3) & 1);
                uint32_t ad = bBase + (uint32_t)((row * 4 + (ch ^ ((row >> 1) & 3))) << 4);
                LDMX4(bfr[nh][0], bfr[nh][1], bfr[nh][2], bfr[nh][3], ad);
            }
#pragma unroll
            for (int mt = 0; mt < 2; mt++)
#pragma unroll
                for (int nt = 0; nt < 4; nt++) {
                    uint32_t b0 = bfr[nt >> 1][(nt & 1) * 2];
                    uint32_t b1 = bfr[nt >> 1][(nt & 1) * 2 + 1];
                    MMA_BF16(acc[mt][nt], afr[mt], b0, b1);
                }
        }
        __syncthreads();
    }

    // ---- epilogue: write split-K partial ----
    float* P = &g_part[z][0];
    const int g2 = lane >> 2, tg = lane & 3;
#pragma unroll
    for (int mt = 0; mt < 2; mt++)
#pragma unroll
        for (int nt = 0; nt < 4; nt++) {
            int r  = bm + wm + mt * 16 + g2;
            int cc = bn + wn + nt * 8 + tg * 2;
            *(float2*)&P[(size_t)r * OUTF + cc] =
                make_float2(acc[mt][nt][0], acc[mt][nt][1]);
            *(float2*)&P[(size_t)(r + 8) * OUTF + cc] =
                make_float2(acc[mt][nt][2], acc[mt][nt][3]);
        }
}

// ---------------------------------------------------------------------------
__global__ void reduce_kernel(float* __restrict__ out) {
    int i = blockIdx.x * blockDim.x + threadIdx.x;
    if (i >= BATCH * OUTF) return;
    out[i] = (g_part[0][i] + g_part[1][i]) + (g_part[2][i] + g_part[3][i]);
}

// ---------------------------------------------------------------------------
extern "C" void kernel_launch(void* const* d_in, const int* in_sizes, int n_in,
                              void* d_out, int out_size) {
    const float* x             = (const float*)d_in[0];
    const float* grid          = (const float*)d_in[1];
    const float* coeff         = (const float*)d_in[2];
    const float* base_weight   = (const float*)d_in[3];
    const float* spline_weight = (const float*)d_in[4];
    float* out = (float*)d_out;

    prep_f_kernel<<<(BATCH * INF + 255) / 256, 256>>>(x, grid);
    prep_w_kernel<<<(OUTF * INF + 255) / 256, 256>>>(coeff, base_weight, spline_weight);

    dim3 g(BATCH / BM, OUTF / BN, NSPLIT);
    gemm_kernel<<<g, 256>>>();

    reduce_kernel<<<(BATCH * OUTF + 255) / 256, 256>>>(out);
}

// round 3
// speedup vs baseline: 2.6788x; 1.5606x over previous
#include <cuda_runtime.h>
#include <cuda_bf16.h>
#include <math.h>
#include <stdint.h>

#define BATCH 1024
#define INF   256
#define OUTF  256
#define NBF   9
#define KD    2304          // NBF * INF, per pass; k = n*INF + i
#define NSPLIT 4
#define BK    32
#define IT_PASS  72         // 2304/32
#define IT_SPLIT 54         // 216/4
#define BM 128
#define BN 64
#define NSTAGE 3

// ---- scratch (__device__ globals: allocation-free rule) ----
__device__ __nv_bfloat16 g_Fh[(size_t)BATCH * KD];
__device__ __nv_bfloat16 g_Fl[(size_t)BATCH * KD];
__device__ __nv_bfloat16 g_Wh[(size_t)OUTF * KD];
__device__ __nv_bfloat16 g_Wl[(size_t)OUTF * KD];
__device__ float g_part[NSPLIT][(size_t)BATCH * OUTF];

// ---------------------------------------------------------------------------
// prep_f: cubic B-spline basis + silu -> bf16 hi/lo split.
// K layout: k = n*INF + i  => warp (consecutive i) stores are coalesced.
// Uniform grid (h = 0.4): denominators are compile-time reciprocals.
// ---------------------------------------------------------------------------
__global__ void prep_f_kernel(const float* __restrict__ x,
                              const float* __restrict__ grid) {
    int t = blockIdx.x * blockDim.x + threadIdx.x;
    if (t >= BATCH * INF) return;
    int b = t >> 8;            // / INF
    int i = t & 255;           // % INF
    float xv = x[t];

    float g[12];
#pragma unroll
    for (int j = 0; j < 12; j++) g[j] = __ldg(grid + j);

    float bas[11];
#pragma unroll
    for (int j = 0; j < 11; j++)
        bas[j] = (xv >= g[j] && xv < g[j + 1]) ? 1.0f : 0.0f;

    const float r1 = 2.5f;            // 1/(1*h)
    const float r2 = 1.25f;           // 1/(2*h)
    const float r3 = 0.83333333333f;  // 1/(3*h)

#pragma unroll
    for (int j = 0; j < 10; j++)      // p = 1
        bas[j] = (xv - g[j]) * r1 * bas[j] + (g[j + 2] - xv) * r1 * bas[j + 1];
#pragma unroll
    for (int j = 0; j < 9; j++)       // p = 2
        bas[j] = (xv - g[j]) * r2 * bas[j] + (g[j + 3] - xv) * r2 * bas[j + 1];
#pragma unroll
    for (int j = 0; j < 8; j++)       // p = 3
        bas[j] = (xv - g[j]) * r3 * bas[j] + (g[j + 4] - xv) * r3 * bas[j + 1];

    bas[7] += (xv >= g[8]) ? 1.0f : 0.0f;

    float e  = __expf(-xv);
    float si = __fdividef(xv, 1.0f + e);

    size_t rowb = (size_t)b * KD + i;     // + n*INF per basis
#pragma unroll
    for (int n = 0; n < 8; n++) {
        float f = bas[n];
        __nv_bfloat16 h = __float2bfloat16(f);
        g_Fh[rowb + n * INF] = h;
        g_Fl[rowb + n * INF] = __float2bfloat16(f - __bfloat162float(h));
    }
    {
        __nv_bfloat16 h = __float2bfloat16(si);
        g_Fh[rowb + 8 * INF] = h;
        g_Fl[rowb + 8 * INF] = __float2bfloat16(si - __bfloat162float(h));
    }
}

// ---------------------------------------------------------------------------
// prep_w: W[o][n*INF+i] = coeff[o,i,n]*spline_w[o,i] (n<8); [8*INF+i]=base_w.
// Coalesced bf16 stores per n across the warp.
// ---------------------------------------------------------------------------
__global__ void prep_w_kernel(const float* __restrict__ coeff,
                              const float* __restrict__ base_weight,
                              const float* __restrict__ spline_weight) {
    int t = blockIdx.x * blockDim.x + threadIdx.x;
    if (t >= OUTF * INF) return;
    int o = t >> 8;
    int i = t & 255;
    float s = spline_weight[t];
    const float4* c4 = (const float4*)(coeff + (size_t)t * 8);
    float4 c0 = c4[0], c1 = c4[1];
    float cv[8] = {c0.x, c0.y, c0.z, c0.w, c1.x, c1.y, c1.z, c1.w};

    size_t rowb = (size_t)o * KD + i;
#pragma unroll
    for (int n = 0; n < 8; n++) {
        float f = cv[n] * s;
        __nv_bfloat16 h = __float2bfloat16(f);
        g_Wh[rowb + n * INF] = h;
        g_Wl[rowb + n * INF] = __float2bfloat16(f - __bfloat162float(h));
    }
    {
        float f = base_weight[t];
        __nv_bfloat16 h = __float2bfloat16(f);
        g_Wh[rowb + 8 * INF] = h;
        g_Wl[rowb + 8 * INF] = __float2bfloat16(f - __bfloat162float(h));
    }
}

// ---------------------------------------------------------------------------
// GEMM: C = Fh*Wh^T + Fl*Wh^T + Fh*Wl^T  (3 K-passes, K_eff = 6912)
// mma.sync m16n8k16 bf16, BM=128 BN=64 BK=32, 8 warps, split-K x4,
// cp.async 3-stage pipeline, XOR-swizzled smem. grid (8,4,4) = 128 CTAs.
// ---------------------------------------------------------------------------
#define A_TILE_B (BM * 64)
#define B_TILE_B (BN * 64)
#define STAGE_B  (A_TILE_B + B_TILE_B)

#define CP16(dst_u32, src_ptr) \
    asm volatile("cp.async.cg.shared.global [%0], [%1], 16;\n" \
                 :: "r"(dst_u32), "l"(src_ptr))

#define LDMX4(r0,r1,r2,r3, addr) \
    asm volatile("ldmatrix.sync.aligned.m8n8.x4.shared.b16 {%0,%1,%2,%3}, [%4];\n" \
                 : "=r"(r0),"=r"(r1),"=r"(r2),"=r"(r3) : "r"(addr))

#define MMA_BF16(d, a, b0_, b1_) \
    asm volatile("mma.sync.aligned.m16n8k16.row.col.f32.bf16.bf16.f32 " \
                 "{%0,%1,%2,%3},{%4,%5,%6,%7},{%8,%9},{%0,%1,%2,%3};\n" \
                 : "+f"(d[0]),"+f"(d[1]),"+f"(d[2]),"+f"(d[3]) \
                 : "r"(a[0]),"r"(a[1]),"r"(a[2]),"r"(a[3]),"r"(b0_),"r"(b1_))

__global__ __launch_bounds__(256, 1)
void gemm_kernel() {
    __shared__ __align__(16) uint8_t smem[NSTAGE * STAGE_B];

    const int tid  = threadIdx.x;
    const int warp = tid >> 5;
    const int lane = tid & 31;
    const int bm = blockIdx.x * BM;
    const int bn = blockIdx.y * BN;
    const int z  = blockIdx.z;
    const int wm = (warp >> 1) * 32;
    const int wn = (warp & 1) * 32;

    const uint32_t smem_u32 = (uint32_t)__cvta_generic_to_shared(smem);

    auto load_tile = [&](int stage, int it) {
        int p  = it / IT_PASS;
        int k0 = (it - p * IT_PASS) * BK;
        const __nv_bfloat16* Ab = (p == 1) ? g_Fl : g_Fh;
        const __nv_bfloat16* Bb = (p == 2) ? g_Wl : g_Wh;
        uint32_t sA = smem_u32 + stage * STAGE_B;
        uint32_t sB = sA + A_TILE_B;
#pragma unroll
        for (int h = 0; h < 2; h++) {
            int slot = tid + h * 256;
            int row = slot >> 2, c = slot & 3;
            const __nv_bfloat16* gp = Ab + (size_t)(bm + row) * KD + k0 + c * 8;
            uint32_t d = sA + (uint32_t)((row * 4 + (c ^ ((row >> 1) & 3))) << 4);
            CP16(d, gp);
        }
        {
            int row = tid >> 2, c = tid & 3;
            const __nv_bfloat16* gp = Bb + (size_t)(bn + row) * KD + k0 + c * 8;
            uint32_t d = sB + (uint32_t)((row * 4 + (c ^ ((row >> 1) & 3))) << 4);
            CP16(d, gp);
        }
        asm volatile("cp.async.commit_group;\n" ::);
    };

    float acc[2][4][4];
#pragma unroll
    for (int a = 0; a < 2; a++)
#pragma unroll
        for (int b = 0; b < 4; b++)
#pragma unroll
            for (int c = 0; c < 4; c++) acc[a][b][c] = 0.0f;

    const int it0 = z * IT_SPLIT;
    load_tile(0, it0);
    load_tile(1, it0 + 1);

    for (int t = 0; t < IT_SPLIT; t++) {
        int nx = t + NSTAGE - 1;
        if (nx < IT_SPLIT) load_tile((t + 2) % NSTAGE, it0 + nx);
        else asm volatile("cp.async.commit_group;\n" ::);
        asm volatile("cp.async.wait_group 2;\n" ::);
        __syncthreads();

        int stage = t % NSTAGE;
        uint32_t aBase = smem_u32 + stage * STAGE_B;
        uint32_t bBase = aBase + A_TILE_B;

#pragma unroll
        for (int kk = 0; kk < 2; kk++) {
            uint32_t afr[2][4];
#pragma unroll
            for (int mt = 0; mt < 2; mt++) {
                int row = wm + mt * 16 + (lane & 15);
                int ch  = kk * 2 + (lane >> 4);
                uint32_t ad = aBase + (uint32_t)((row * 4 + (ch ^ ((row >> 1) & 3))) << 4);
                LDMX4(afr[mt][0], afr[mt][1], afr[mt][2], afr[mt][3], ad);
            }
            uint32_t bfr[2][4];
#pragma unroll
            for (int nh = 0; nh < 2; nh++) {
                int row = wn + nh * 16 + ((lane >> 4) << 3) + (lane & 7);
                int ch  = kk * 2 + ((lane >> 3) & 1);
                uint32_t ad = bBase + (uint32_t)((row * 4 + (ch ^ ((row >> 1) & 3))) << 4);
                LDMX4(bfr[nh][0], bfr[nh][1], bfr[nh][2], bfr[nh][3], ad);
            }
#pragma unroll
            for (int mt = 0; mt < 2; mt++)
#pragma unroll
                for (int nt = 0; nt < 4; nt++) {
                    uint32_t b0 = bfr[nt >> 1][(nt & 1) * 2];
                    uint32_t b1 = bfr[nt >> 1][(nt & 1) * 2 + 1];
                    MMA_BF16(acc[mt][nt], afr[mt], b0, b1);
                }
        }
        __syncthreads();
    }

    float* P = &g_part[z][0];
    const int g2 = lane >> 2, tg = lane & 3;
#pragma unroll
    for (int mt = 0; mt < 2; mt++)
#pragma unroll
        for (int nt = 0; nt < 4; nt++) {
            int r  = bm + wm + mt * 16 + g2;
            int cc = bn + wn + nt * 8 + tg * 2;
            *(float2*)&P[(size_t)r * OUTF + cc] =
                make_float2(acc[mt][nt][0], acc[mt][nt][1]);
            *(float2*)&P[(size_t)(r + 8) * OUTF + cc] =
                make_float2(acc[mt][nt][2], acc[mt][nt][3]);
        }
}

// ---------------------------------------------------------------------------
// reduce: float4 grid-stride, 256 CTAs x 256 thr, 1 float4/thread.
// ---------------------------------------------------------------------------
__global__ void reduce_kernel(float* __restrict__ out) {
    int i = blockIdx.x * blockDim.x + threadIdx.x;        // float4 index
    const float4* p0 = (const float4*)&g_part[0][0];
    const float4* p1 = (const float4*)&g_part[1][0];
    const float4* p2 = (const float4*)&g_part[2][0];
    const float4* p3 = (const float4*)&g_part[3][0];
    float4 a = p0[i], b = p1[i], c = p2[i], d = p3[i];
    float4 r;
    r.x = (a.x + b.x) + (c.x + d.x);
    r.y = (a.y + b.y) + (c.y + d.y);
    r.z = (a.z + b.z) + (c.z + d.z);
    r.w = (a.w + b.w) + (c.w + d.w);
    ((float4*)out)[i] = r;
}

// ---------------------------------------------------------------------------
extern "C" void kernel_launch(void* const* d_in, const int* in_sizes, int n_in,
                              void* d_out, int out_size) {
    const float* x             = (const float*)d_in[0];
    const float* grid          = (const float*)d_in[1];
    const float* coeff         = (const float*)d_in[2];
    const float* base_weight   = (const float*)d_in[3];
    const float* spline_weight = (const float*)d_in[4];
    float* out = (float*)d_out;

    prep_f_kernel<<<(BATCH * INF + 255) / 256, 256>>>(x, grid);
    prep_w_kernel<<<(OUTF * INF + 255) / 256, 256>>>(coeff, base_weight, spline_weight);

    dim3 g(BATCH / BM, OUTF / BN, NSPLIT);
    gemm_kernel<<<g, 256>>>();

    reduce_kernel<<<(BATCH * OUTF / 4 + 255) / 256, 256>>>(out);
}